// round 13
// baseline (speedup 1.0000x reference)
#include <cuda_runtime.h>
#include <cuda_bf16.h>

#define K 64
#define T 1024
#define F 1025
#define NCTRL 257
#define H 16
#define FP 5
#define NACT 205
#define TFLOOR (1.0f - 0.9f)
#define NFIX 4
#define TFIX (T / NFIX)
#define SAL_MARGIN 2.0f

__device__ __forceinline__ float ex2a(float x) {
    float y; asm("ex2.approx.f32 %0, %1;" : "=f"(y) : "f"(x)); return y;
}
__device__ __forceinline__ float sqrta(float x) {
    float y; asm("sqrt.approx.f32 %0, %1;" : "=f"(y) : "f"(x)); return y;
}

struct Bind {
    const void *mu, *sig, *path, *alpha, *phase, *harm;
    int n_mu, n_sig, n_path, n_alpha, n_phase, n_harm;
    int isbf;
};
__device__ Bind g_B;

__device__ float4 g_P4[K * T];     // freq, 1/freq, alpha*cos(ph), alpha*sin(ph)
__device__ float  g_alphaK[K * T];
__device__ float4 g_KC[K];         // c0, c1, 8*sigma, sigma            (scan/fixup)
__device__ float4 g_KT1[K];        // s2*1.2533, isr2, w2=8*s2, s2*2.5066 (ktsal)
__device__ float4 g_KT2[K];        // h1*s1*1.2533, isr1, w1=8*s1, qflag  (ktsal)
__device__ float  g_cumh[K * 17];  // cumh[n] = sum_{m=2..n} h_m (cumh[0..1]=0)
__device__ float  g_harmS[K * H];
__device__ float  g_partial[K * 4];
__device__ float  g_fix[K * NFIX];
__device__ int    g_ord[K];

__device__ __forceinline__ float ldin(const void* p, int i, int n, int isbf) {
    if (p == 0) return 0.0f;
    int j = i; if (j > n - 1) j = n - 1; if (j < 0) j = 0;
    if (isbf) return __bfloat162float(((const __nv_bfloat16*)p)[j]);
    return ((const float*)p)[j];
}

// ---------- kernel 1: bind inputs + per-k constants (one CTA) ----------
__global__ void bindprep_kernel(const void* p0, int s0, const void* p1, int s1,
                                const void* p2, int s2, const void* p3, int s3,
                                const void* p4, int s4, const void* p5, int s5) {
    __shared__ float red[256];
    __shared__ float mabs[6];
    __shared__ int   nel[6];
    __shared__ int   sAbs, sTot, sBF;
    const void* ps[6] = {p0, p1, p2, p3, p4, p5};
    int ss[6] = {s0, s1, s2, s3, s4, s5};
    int tid = threadIdx.x;

    if (tid == 0) {
        for (int j = 0; j < 6; ++j) {
            int n = ss[j], ne;
            if      (n == K || n == K * 2 || n == K * 4)                         ne = K;
            else if (n == K * H || n == K * H * 2 || n == K * H * 4)             ne = K * H;
            else if (n == K * NCTRL || n == K * NCTRL * 2 || n == K * NCTRL * 4) ne = K * NCTRL;
            else                                                                  ne = 0;
            nel[j] = (ps[j] != 0) ? ne : 0;
        }
        sAbs = 0; sTot = 0;
    }
    __syncthreads();

    int myA = 0, myT = 0;
    for (int j = 0; j < 6; ++j) {
        int lw = nel[j] / 2; if (lw > 256) lw = 256;
        const unsigned* w = (const unsigned*)ps[j];
        if (w) for (int i = tid; i < lw; i += 256) {
            unsigned lo = w[i] & 0xFFFFu;
            if (lo != 0u && lo != 0x8000u) {
                int e = (int)((lo >> 7) & 0xFFu);
                ++myT;
                if (e < 90 || e > 164) ++myA;
            }
        }
    }
    atomicAdd(&sAbs, myA);
    atomicAdd(&sTot, myT);
    __syncthreads();
    if (tid == 0) sBF = (sTot > 32 && sAbs * 100 < sTot * 35) ? 1 : 0;
    __syncthreads();
    int isbf = sBF;

    for (int j = 0; j < 6; ++j) {
        int lim = nel[j] / 2; if (lim > 256) lim = 256;
        float s = 0.0f;
        if (ps[j]) for (int i = tid; i < lim; i += 256) s += fabsf(ldin(ps[j], i, lim, isbf));
        red[tid] = s;
        __syncthreads();
        for (int st = 128; st > 0; st >>= 1) {
            if (tid < st) red[tid] += red[tid + st];
            __syncthreads();
        }
        if (tid == 0) mabs[j] = (lim > 0) ? red[0] / (float)lim : -1.0f;
        __syncthreads();
    }

    if (tid == 0) {
        int sm[2]; int nsm = 0;
        int ct[3]; int nct = 0;
        int ih = -1;
        for (int j = 0; j < 6; ++j) {
            if (nel[j] == K && nsm < 2)              sm[nsm++] = j;
            else if (nel[j] == K * H && ih < 0)      ih = j;
            else if (nel[j] == K * NCTRL && nct < 3) ct[nct++] = j;
        }
        Bind b;
        b.isbf = isbf;
        if (nsm == 2 && nct == 3 && ih >= 0) {
            int imu  = (mabs[sm[0]] >= mabs[sm[1]]) ? sm[0] : sm[1];
            int isig = (imu == sm[0]) ? sm[1] : sm[0];
            int a = ct[0], c = ct[1], d = ct[2];
            if (mabs[a] < mabs[c]) { int t_ = a; a = c; c = t_; }
            if (mabs[c] < mabs[d]) { int t_ = c; c = d; d = t_; }
            if (mabs[a] < mabs[c]) { int t_ = a; a = c; c = t_; }
            b.mu    = ps[imu];  b.n_mu    = nel[imu];
            b.sig   = ps[isig]; b.n_sig   = nel[isig];
            b.path  = ps[a];    b.n_path  = nel[a];
            b.alpha = ps[c];    b.n_alpha = nel[c];
            b.phase = ps[d];    b.n_phase = nel[d];
            b.harm  = ps[ih];   b.n_harm  = nel[ih];
        } else {
            const void* fb = 0;
            for (int j = 0; j < 6; ++j) if (ps[j]) { fb = ps[j]; break; }
            b.mu    = ps[0] ? ps[0] : fb;  b.n_mu    = (nel[0] > 0) ? nel[0] : 1;
            b.sig   = ps[1] ? ps[1] : fb;  b.n_sig   = (nel[1] > 0) ? nel[1] : 1;
            b.path  = ps[2] ? ps[2] : fb;  b.n_path  = (nel[2] > 0) ? nel[2] : 1;
            b.alpha = ps[3] ? ps[3] : fb;  b.n_alpha = (nel[3] > 0) ? nel[3] : 1;
            b.harm  = ps[4] ? ps[4] : fb;  b.n_harm  = (nel[4] > 0) ? nel[4] : 1;
            b.phase = ps[5] ? ps[5] : fb;  b.n_phase = (nel[5] > 0) ? nel[5] : 1;
        }
        g_B = b;
    }
    __syncthreads();

    int k = tid;
    if (k < K) {
        int bf16 = g_B.isbf;
        float sigma = __expf(ldin(g_B.sig, k, g_B.n_sig, bf16));
        sigma = fminf(fmaxf(sigma, 0.5f), 60.0f);
        float c0 = -0.72134752044f / (sigma * sigma);
        g_KC[k] = make_float4(c0, c0 / 0.49f, 8.0f * sigma, sigma);

        float l[H];
        float mx = -1e30f;
        #pragma unroll
        for (int h = 0; h < H; ++h) { l[h] = ldin(g_B.harm, k * H + h, g_B.n_harm, bf16); mx = fmaxf(mx, l[h]); }
        float s = 0.0f;
        #pragma unroll
        for (int h = 0; h < H; ++h) { l[h] = __expf(l[h] - mx); s += l[h]; }
        float inv = 1.0f / s;
        #pragma unroll
        for (int h = 0; h < H; ++h) { l[h] *= inv; g_harmS[k * H + h] = l[h]; }

        // ktsal constants
        float s1 = sigma, s2v = 0.7f * sigma;
        g_KT1[k] = make_float4(s2v * 1.25331414f, 0.70710678f / s2v, 8.0f * s2v, s2v * 2.50662827f);
        float qflag = (s2v < 1.0f) ? 1.0f : 0.0f;   // theta correction needed only for tiny sigma
        g_KT2[k] = make_float4(l[0] * s1 * 1.25331414f, 0.70710678f / s1, 8.0f * s1, qflag);

        // cumulative harmonic weights for n>=2: cumh[n] = sum_{m=2..n} h_m
        float cum = 0.0f;
        g_cumh[k * 17 + 0] = 0.0f;
        g_cumh[k * 17 + 1] = 0.0f;
        #pragma unroll
        for (int n = 2; n <= H; ++n) { cum += l[n - 1]; g_cumh[k * 17 + n] = cum; }
    }
}

// ---------- kernel 2: per-(k,t) params + O(1) analytic salience + CTA reduce ----------
__global__ void ktsal_kernel() {
    int idx = blockIdx.x * blockDim.x + threadIdx.x;
    int k = idx >> 10;
    int t = idx & 1023;
    int tid = threadIdx.x;
    int isbf = g_B.isbf;

    __shared__ float shh[H];
    __shared__ float red[256];
    if (tid < H) shh[tid] = g_harmS[(k << 4) + tid];  // CTA spans one k
    __syncthreads();

    float pos = (float)t * (256.0f / 1023.0f);
    int lo = (int)pos;
    if (lo > NCTRL - 2) lo = NCTRL - 2;
    float fr  = pos - (float)lo;
    float omf = 1.0f - fr;
    int b0 = k * NCTRL + lo;
    int b1 = b0 + 1;

    float path = ldin(g_B.path,  b0, g_B.n_path,  isbf) * omf + ldin(g_B.path,  b1, g_B.n_path,  isbf) * fr;
    float av   = ldin(g_B.alpha, b0, g_B.n_alpha, isbf) * omf + ldin(g_B.alpha, b1, g_B.n_alpha, isbf) * fr;
    float ph   = ldin(g_B.phase, b0, g_B.n_phase, isbf) * omf + ldin(g_B.phase, b1, g_B.n_phase, isbf) * fr;

    float alpha = 1.0f / (1.0f + __expf(-av));
    float sp, cp;
    __sincosf(ph, &sp, &cp);

    float freq = ldin(g_B.mu, k, g_B.n_mu, isbf) + path;
    freq = fminf(fmaxf(freq, 3.71519274f), 1024.0f);
    float invf = 1.0f / freq;

    g_P4[idx]     = make_float4(freq, invf, alpha * cp, alpha * sp);
    g_alphaK[idx] = alpha;

    // analytic sum_f sqrt(mag^2+1e-12): interior harmonics = t-independent
    // constants (prefix-summed); only boundary-clipped harmonics need erf.
    float4 kt1 = g_KT1[k];   // a2=s2*1.2533, isr2, w2, full2=s2*2.5066
    float4 kt2 = g_KT2[k];   // a1h=h1*s1*1.2533, isr1, w1, qflag
    float sal;

    // n = 1 (sigma_1)
    if (freq >= kt2.z && freq <= 1024.0f - kt2.z) {
        sal = 2.0f * kt2.x;
    } else {
        sal = kt2.x * (erff((1024.5f - freq) * kt2.y) - erff((-0.5f - freq) * kt2.y));
    }

    // n >= 2 (sigma_2): interior range via prefix sums
    int nloI = max(2, (int)ceilf(kt1.z * invf));
    int nhiI = min(H, (int)floorf((1024.0f - kt1.z) * invf));
    const float* cumh = &g_cumh[k * 17];
    if (nhiI >= nloI) sal += kt1.w * (cumh[nhiI] - cumh[nloI - 1]);

    // left-clipped harmonics (c - w2 < 0)
    for (int n = 2; n < nloI && n <= H; ++n) {
        float c = (float)n * freq;
        sal += shh[n - 1] * kt1.x * (erff((1024.5f - c) * kt1.y) - erff((-0.5f - c) * kt1.y));
    }
    // right-clipped harmonics (c + w2 > 1024)
    for (int n = max(nloI, nhiI + 1); n <= H; ++n) {
        float c = (float)n * freq;
        if (c - kt1.z > 1024.5f) break;
        sal += shh[n - 1] * kt1.x * (erff((1024.5f - c) * kt1.y) - erff((-0.5f - c) * kt1.y));
    }

    // Jacobi theta m=1 correction (only for very small sigma; off for real data)
    if (kt2.w > 0.5f) {
        float s1v = kt2.z * 0.125f, s2v = kt1.z * 0.125f;
        for (int n = 1; n <= H; ++n) {
            float c = (float)n * freq;
            float sn = (n == 1) ? s1v : s2v;
            sal += shh[n - 1] * sn * 5.01325654f * ex2a(-28.4945f * sn * sn) * __cosf(6.2831853f * c);
        }
    }

    // 1e-6 floor midpoint constant (error <= 0.53 absolute; covered by SAL_MARGIN)
    float salt = alpha * (sal + 5.12e-4f);

    // deterministic CTA tree reduce -> one partial per (k, quarter)
    red[tid] = salt;
    __syncthreads();
    for (int s = 128; s > 0; s >>= 1) {
        if (tid < s) red[tid] += red[tid + s];
        __syncthreads();
    }
    if (tid == 0) g_partial[blockIdx.x] = red[0];   // blockIdx.x = k*4 + quarter
}

// ---------- windowed Gaussian mag over FP contiguous bins (fixup only) ----------
__device__ __forceinline__ void eval_mag_group(
    float bf, float freq, float invf, float c0, float c1, float w,
    const float* __restrict__ harm, float m[FP])
{
    #pragma unroll
    for (int i = 0; i < FP; ++i) m[i] = 0.0f;
    int nlo = (int)ceilf((bf - w) * invf);
    int nhi = (int)floorf((bf + (float)(FP - 1) + w) * invf);
    nlo = max(1, nlo);
    nhi = min(H, nhi);
    for (int n = nlo; n <= nhi; ++n) {
        float nf = (float)n * freq;
        float cn = (n == 1) ? c0 : c1;
        float hn = harm[n - 1];
        #pragma unroll
        for (int i = 0; i < FP; ++i) {
            float d = (bf + (float)i) - nf;
            m[i] = fmaf(hn, ex2a(cn * d * d), m[i]);
        }
    }
}

__device__ __forceinline__ int tie_flag(const float* salA, int k) {
    float sk = salA[k];
    int fl = 0;
    #pragma unroll
    for (int j = 0; j < K; ++j)
        if (j != k && fabsf(sk - salA[j]) < SAL_MARGIN) fl = 1;
    return fl;
}

// ---------- kernel 3: exact-field salience fixup (only near-tied k) ----------
__global__ void fixup_kernel() {
    int k = blockIdx.x;
    int chunk = blockIdx.y;
    int tid = threadIdx.x;

    __shared__ float part[256];
    __shared__ float salA[K];
    __shared__ int   sfl;
    __shared__ float shh[H];
    __shared__ float red[256];

    part[tid] = g_partial[tid];
    __syncthreads();
    if (tid < K)
        salA[tid] = part[tid * 4] + part[tid * 4 + 1] + part[tid * 4 + 2] + part[tid * 4 + 3];
    __syncthreads();
    if (tid == 0) sfl = tie_flag(salA, k);
    __syncthreads();
    if (sfl == 0) return;

    if (tid < H) shh[tid] = g_harmS[k * H + tid];
    __syncthreads();

    float4 cc = g_KC[k];
    float acc = 0.0f;
    if (tid < NACT) {
        float bf = (float)(tid * FP);
        int t0 = chunk * TFIX;
        for (int t = t0; t < t0 + TFIX; ++t) {
            float4 p = g_P4[(k << 10) + t];
            float al = g_alphaK[(k << 10) + t];
            float m[FP];
            eval_mag_group(bf, p.x, p.y, cc.x, cc.y, cc.z, shh, m);
            float s = 0.0f;
            #pragma unroll
            for (int i = 0; i < FP; ++i)
                s += (m[i] > 0.0f) ? sqrta(fmaf(m[i], m[i], 1e-12f)) : 1e-6f;
            acc = fmaf(al, s, acc);
        }
    }
    red[tid] = acc;
    __syncthreads();
    for (int s = 128; s > 0; s >>= 1) {
        if (tid < s) red[tid] += red[tid + s];
        __syncthreads();
    }
    if (tid == 0) g_fix[k * NFIX + chunk] = red[0];
}

// ---------- kernel 4: combine + stable descending rank (one CTA) ----------
__global__ void combineorder_kernel() {
    __shared__ float salA[K];
    __shared__ float sal[K];
    int i = threadIdx.x;
    if (i < K)
        salA[i] = g_partial[i * 4] + g_partial[i * 4 + 1] + g_partial[i * 4 + 2] + g_partial[i * 4 + 3];
    __syncthreads();
    if (i < K) {
        float v;
        if (tie_flag(salA, i)) {
            v = 0.0f;
            #pragma unroll
            for (int c = 0; c < NFIX; ++c) v += g_fix[i * NFIX + c];
        } else v = salA[i];
        sal[i] = v;
    }
    __syncthreads();
    if (i < K) {
        float si = sal[i];
        int r = 0;
        #pragma unroll
        for (int j = 0; j < K; ++j) {
            float sj = sal[j];
            r += (sj > si) || (sj == si && j < i);
        }
        g_ord[r] = i;
    }
}

// ---------- kernel 5: ordered composite scan (window-empty skip) ----------
__global__ void scan_kernel(float* __restrict__ out, int capE) {
    int t = blockIdx.x;
    int tid = threadIdx.x;

    __shared__ int    shord[K];
    __shared__ float4 sh4[K];
    __shared__ float  shal[K];
    __shared__ float4 shc[K];
    __shared__ float  shh[K * H];

    if (tid < K) shord[tid] = g_ord[tid] & (K - 1);
    __syncthreads();
    if (tid < K) {
        int kk = shord[tid];
        int o = (kk << 10) + t;
        sh4[tid]  = g_P4[o];
        shal[tid] = g_alphaK[o];
        shc[tid]  = g_KC[kk];
    }
    for (int i = tid; i < K * H; i += blockDim.x)
        shh[i] = g_harmS[(shord[i >> 4] << 4) + (i & 15)];
    __syncthreads();

    if (tid >= NACT) return;
    float bf = (float)(tid * FP);

    float outr[FP], tt[FP];
    #pragma unroll
    for (int i = 0; i < FP; ++i) { outr[i] = 0.0f; tt[i] = 1.0f; }

    for (int j = 0; j < K; ++j) {
        float4 p  = sh4[j];
        float4 cc = shc[j];
        int nlo = max(1, (int)ceilf((bf - cc.z) * p.y));
        int nhi = min(H, (int)floorf((bf + (float)(FP - 1) + cc.z) * p.y));
        if (nlo > nhi) continue;

        float al = shal[j];
        const float* harm = &shh[j << 4];
        float m[FP];
        #pragma unroll
        for (int i = 0; i < FP; ++i) m[i] = 0.0f;
        for (int n = nlo; n <= nhi; ++n) {
            float nf = (float)n * p.x;
            float cn = (n == 1) ? cc.x : cc.y;
            float hn = harm[n - 1];
            #pragma unroll
            for (int i = 0; i < FP; ++i) {
                float d = (bf + (float)i) - nf;
                m[i] = fmaf(hn, ex2a(cn * d * d), m[i]);
            }
        }
        #pragma unroll
        for (int i = 0; i < FP; ++i) {
            float mv = m[i];
            float mc = (mv > 0.0f) ? sqrta(fmaf(mv, mv, 1e-12f)) : 1e-6f;
            float a  = fminf(al * mc, 1.0f);
            outr[i] = fmaf(tt[i] * mv, p.z, outr[i]);
            tt[i]   = fmaxf(fmaf(-a, tt[i], tt[i]), TFLOOR);
        }
    }

    int base = t * F + tid * FP;
    #pragma unroll
    for (int i = 0; i < FP; ++i) {
        int gi = base + i;
        if (gi < capE) out[gi] = outr[i];
    }
}

// ---------- launch ----------
extern "C" void kernel_launch(void* const* d_in, const int* in_sizes, int n_in,
                              void* d_out, int out_size) {
    const void* p[6];
    int s[6];
    for (int i = 0; i < 6; ++i) {
        if (i < n_in) { p[i] = d_in[i]; s[i] = in_sizes[i]; }
        else          { p[i] = 0; s[i] = 0; }
    }

    int capE = out_size;
    if (capE > T * F) capE = T * F;
    if (capE < 0) capE = 0;

    bindprep_kernel<<<1, 256>>>(p[0], s[0], p[1], s[1], p[2], s[2],
                                p[3], s[3], p[4], s[4], p[5], s[5]);
    ktsal_kernel<<<(K * T) / 256, 256>>>();
    fixup_kernel<<<dim3(K, NFIX), 256>>>();
    combineorder_kernel<<<1, 64>>>();
    scan_kernel<<<T, 224>>>((float*)d_out, capE);
}

// round 14
// speedup vs baseline: 2.0412x; 2.0412x over previous
#include <cuda_runtime.h>
#include <cuda_bf16.h>

#define K 64
#define T 1024
#define F 1025
#define NCTRL 257
#define H 16
#define FP 5
#define NACT 205
#define TFLOOR (1.0f - 0.9f)
#define NFIX 4
#define TFIX (T / NFIX)
#define SAL_MARGIN 1.0f

__device__ __forceinline__ float ex2a(float x) {
    float y; asm("ex2.approx.f32 %0, %1;" : "=f"(y) : "f"(x)); return y;
}
__device__ __forceinline__ float sqrta(float x) {
    float y; asm("sqrt.approx.f32 %0, %1;" : "=f"(y) : "f"(x)); return y;
}

struct Bind {
    const void *mu, *sig, *path, *alpha, *phase, *harm;
    int n_mu, n_sig, n_path, n_alpha, n_phase, n_harm;
    int isbf;
};
__device__ Bind g_B;

__device__ float4 g_P4[K * T];     // freq, 1/freq, alpha*cos(ph), alpha*sin(ph)
__device__ float  g_alphaK[K * T];
__device__ float4 g_KC[K];         // c0, c1, 8*sigma, sigma            (scan/fixup)
__device__ float4 g_KT1[K];        // s2*1.2533, isr2, w2=8*s2, s2*2.5066 (ktsal)
__device__ float4 g_KT2[K];        // h1*s1*1.2533, isr1, w1=8*s1, s2     (ktsal)
__device__ float  g_cumh[K * 17];  // cumh[n] = sum_{m=2..n} h_m (cumh[0..1]=0)
__device__ float  g_harmS[K * H];
__device__ float  g_partial[K * 4];
__device__ float  g_fix[K * NFIX];
__device__ int    g_ord[K];

__device__ __forceinline__ float ldin(const void* p, int i, int n, int isbf) {
    if (p == 0) return 0.0f;
    int j = i; if (j > n - 1) j = n - 1; if (j < 0) j = 0;
    if (isbf) return __bfloat162float(((const __nv_bfloat16*)p)[j]);
    return ((const float*)p)[j];
}

// ---------- kernel 1: bind inputs + per-k constants (one CTA) ----------
__global__ void bindprep_kernel(const void* p0, int s0, const void* p1, int s1,
                                const void* p2, int s2, const void* p3, int s3,
                                const void* p4, int s4, const void* p5, int s5) {
    __shared__ float red[256];
    __shared__ float mabs[6];
    __shared__ int   nel[6];
    __shared__ int   sAbs, sTot, sBF;
    const void* ps[6] = {p0, p1, p2, p3, p4, p5};
    int ss[6] = {s0, s1, s2, s3, s4, s5};
    int tid = threadIdx.x;

    if (tid == 0) {
        for (int j = 0; j < 6; ++j) {
            int n = ss[j], ne;
            if      (n == K || n == K * 2 || n == K * 4)                         ne = K;
            else if (n == K * H || n == K * H * 2 || n == K * H * 4)             ne = K * H;
            else if (n == K * NCTRL || n == K * NCTRL * 2 || n == K * NCTRL * 4) ne = K * NCTRL;
            else                                                                  ne = 0;
            nel[j] = (ps[j] != 0) ? ne : 0;
        }
        sAbs = 0; sTot = 0;
    }
    __syncthreads();

    int myA = 0, myT = 0;
    for (int j = 0; j < 6; ++j) {
        int lw = nel[j] / 2; if (lw > 256) lw = 256;
        const unsigned* w = (const unsigned*)ps[j];
        if (w) for (int i = tid; i < lw; i += 256) {
            unsigned lo = w[i] & 0xFFFFu;
            if (lo != 0u && lo != 0x8000u) {
                int e = (int)((lo >> 7) & 0xFFu);
                ++myT;
                if (e < 90 || e > 164) ++myA;
            }
        }
    }
    atomicAdd(&sAbs, myA);
    atomicAdd(&sTot, myT);
    __syncthreads();
    if (tid == 0) sBF = (sTot > 32 && sAbs * 100 < sTot * 35) ? 1 : 0;
    __syncthreads();
    int isbf = sBF;

    for (int j = 0; j < 6; ++j) {
        int lim = nel[j] / 2; if (lim > 256) lim = 256;
        float s = 0.0f;
        if (ps[j]) for (int i = tid; i < lim; i += 256) s += fabsf(ldin(ps[j], i, lim, isbf));
        red[tid] = s;
        __syncthreads();
        for (int st = 128; st > 0; st >>= 1) {
            if (tid < st) red[tid] += red[tid + st];
            __syncthreads();
        }
        if (tid == 0) mabs[j] = (lim > 0) ? red[0] / (float)lim : -1.0f;
        __syncthreads();
    }

    if (tid == 0) {
        int sm[2]; int nsm = 0;
        int ct[3]; int nct = 0;
        int ih = -1;
        for (int j = 0; j < 6; ++j) {
            if (nel[j] == K && nsm < 2)              sm[nsm++] = j;
            else if (nel[j] == K * H && ih < 0)      ih = j;
            else if (nel[j] == K * NCTRL && nct < 3) ct[nct++] = j;
        }
        Bind b;
        b.isbf = isbf;
        if (nsm == 2 && nct == 3 && ih >= 0) {
            int imu  = (mabs[sm[0]] >= mabs[sm[1]]) ? sm[0] : sm[1];
            int isig = (imu == sm[0]) ? sm[1] : sm[0];
            int a = ct[0], c = ct[1], d = ct[2];
            if (mabs[a] < mabs[c]) { int t_ = a; a = c; c = t_; }
            if (mabs[c] < mabs[d]) { int t_ = c; c = d; d = t_; }
            if (mabs[a] < mabs[c]) { int t_ = a; a = c; c = t_; }
            b.mu    = ps[imu];  b.n_mu    = nel[imu];
            b.sig   = ps[isig]; b.n_sig   = nel[isig];
            b.path  = ps[a];    b.n_path  = nel[a];
            b.alpha = ps[c];    b.n_alpha = nel[c];
            b.phase = ps[d];    b.n_phase = nel[d];
            b.harm  = ps[ih];   b.n_harm  = nel[ih];
        } else {
            const void* fb = 0;
            for (int j = 0; j < 6; ++j) if (ps[j]) { fb = ps[j]; break; }
            b.mu    = ps[0] ? ps[0] : fb;  b.n_mu    = (nel[0] > 0) ? nel[0] : 1;
            b.sig   = ps[1] ? ps[1] : fb;  b.n_sig   = (nel[1] > 0) ? nel[1] : 1;
            b.path  = ps[2] ? ps[2] : fb;  b.n_path  = (nel[2] > 0) ? nel[2] : 1;
            b.alpha = ps[3] ? ps[3] : fb;  b.n_alpha = (nel[3] > 0) ? nel[3] : 1;
            b.harm  = ps[4] ? ps[4] : fb;  b.n_harm  = (nel[4] > 0) ? nel[4] : 1;
            b.phase = ps[5] ? ps[5] : fb;  b.n_phase = (nel[5] > 0) ? nel[5] : 1;
        }
        g_B = b;
    }
    __syncthreads();

    int k = tid;
    if (k < K) {
        int bf16 = g_B.isbf;
        float sigma = __expf(ldin(g_B.sig, k, g_B.n_sig, bf16));
        sigma = fminf(fmaxf(sigma, 0.5f), 60.0f);
        float c0 = -0.72134752044f / (sigma * sigma);
        g_KC[k] = make_float4(c0, c0 / 0.49f, 8.0f * sigma, sigma);

        float l[H];
        float mx = -1e30f;
        #pragma unroll
        for (int h = 0; h < H; ++h) { l[h] = ldin(g_B.harm, k * H + h, g_B.n_harm, bf16); mx = fmaxf(mx, l[h]); }
        float s = 0.0f;
        #pragma unroll
        for (int h = 0; h < H; ++h) { l[h] = __expf(l[h] - mx); s += l[h]; }
        float inv = 1.0f / s;
        #pragma unroll
        for (int h = 0; h < H; ++h) { l[h] *= inv; g_harmS[k * H + h] = l[h]; }

        float s1 = sigma, s2v = 0.7f * sigma;
        g_KT1[k] = make_float4(s2v * 1.25331414f, 0.70710678f / s2v, 8.0f * s2v, s2v * 2.50662827f);
        g_KT2[k] = make_float4(l[0] * s1 * 1.25331414f, 0.70710678f / s1, 8.0f * s1, s2v);

        float cum = 0.0f;
        g_cumh[k * 17 + 0] = 0.0f;
        g_cumh[k * 17 + 1] = 0.0f;
        #pragma unroll
        for (int n = 2; n <= H; ++n) { cum += l[n - 1]; g_cumh[k * 17 + n] = cum; }
    }
}

// ---------- kernel 2: per-(k,t) params + analytic salience (exact U) + CTA reduce ----------
__global__ void ktsal_kernel() {
    int idx = blockIdx.x * blockDim.x + threadIdx.x;
    int k = idx >> 10;
    int t = idx & 1023;
    int tid = threadIdx.x;
    int isbf = g_B.isbf;

    __shared__ float shh[H];
    __shared__ float red[256];
    if (tid < H) shh[tid] = g_harmS[(k << 4) + tid];  // CTA spans one k
    __syncthreads();

    float pos = (float)t * (256.0f / 1023.0f);
    int lo = (int)pos;
    if (lo > NCTRL - 2) lo = NCTRL - 2;
    float fr  = pos - (float)lo;
    float omf = 1.0f - fr;
    int b0 = k * NCTRL + lo;
    int b1 = b0 + 1;

    float path = ldin(g_B.path,  b0, g_B.n_path,  isbf) * omf + ldin(g_B.path,  b1, g_B.n_path,  isbf) * fr;
    float av   = ldin(g_B.alpha, b0, g_B.n_alpha, isbf) * omf + ldin(g_B.alpha, b1, g_B.n_alpha, isbf) * fr;
    float ph   = ldin(g_B.phase, b0, g_B.n_phase, isbf) * omf + ldin(g_B.phase, b1, g_B.n_phase, isbf) * fr;

    float alpha = 1.0f / (1.0f + __expf(-av));
    float sp, cp;
    __sincosf(ph, &sp, &cp);

    float freq = ldin(g_B.mu, k, g_B.n_mu, isbf) + path;
    freq = fminf(fmaxf(freq, 3.71519274f), 1024.0f);
    float invf = 1.0f / freq;

    g_P4[idx]     = make_float4(freq, invf, alpha * cp, alpha * sp);
    g_alphaK[idx] = alpha;

    // analytic sum_f sqrt(mag^2+1e-12): interior harmonics via prefix sums,
    // boundary-clipped via erf; EXACT 1e-6-floor bin count U (interval union).
    float4 kt1 = g_KT1[k];   // a2=s2*1.2533, isr2, w2, full2=s2*2.5066
    float4 kt2 = g_KT2[k];   // a1h=h1*s1*1.2533, isr1, w1, s2
    float sal;

    // n = 1 (sigma_1)
    if (freq >= kt2.z && freq <= 1024.0f - kt2.z) {
        sal = 2.0f * kt2.x;
    } else {
        sal = kt2.x * (erff((1024.5f - freq) * kt2.y) - erff((-0.5f - freq) * kt2.y));
    }

    // n >= 2 (sigma_2): interior range via prefix sums
    int nloI = max(2, (int)ceilf(kt1.z * invf));
    int nhiI = min(H, (int)floorf((1024.0f - kt1.z) * invf));
    const float* cumh = &g_cumh[k * 17];
    if (nhiI >= nloI) sal += kt1.w * (cumh[nhiI] - cumh[nloI - 1]);

    // left-clipped harmonics
    for (int n = 2; n < nloI && n <= H; ++n) {
        float c = (float)n * freq;
        sal += shh[n - 1] * kt1.x * (erff((1024.5f - c) * kt1.y) - erff((-0.5f - c) * kt1.y));
    }
    // right-clipped harmonics
    for (int n = max(nloI, nhiI + 1); n <= H; ++n) {
        float c = (float)n * freq;
        if (c - kt1.z > 1024.5f) break;
        sal += shh[n - 1] * kt1.x * (erff((1024.5f - c) * kt1.y) - erff((-0.5f - c) * kt1.y));
    }

    // exact union count of bins where any gaussian >= 1e-6 (matches R12)
    float s1v = kt2.z * 0.125f, s2v = kt2.w;
    int U = 0, lastbin = -1;
    #pragma unroll 1
    for (int n = 1; n <= H; ++n) {
        float c  = (float)n * freq;
        float sn = (n == 1) ? s1v : s2v;
        if (c - 8.0f * sn > 1024.5f) break;
        float hn = shh[n - 1];
        if (hn > 1e-6f) {
            float dn = sn * sqrta(2.0f * (__logf(hn) + 13.8155106f));
            int ulo = (int)ceilf(c - dn);
            if (ulo < lastbin + 1) ulo = lastbin + 1;
            if (ulo < 0) ulo = 0;
            int uhi = (int)floorf(c + dn);
            if (uhi > 1024) uhi = 1024;
            if (uhi >= ulo) { U += uhi - ulo + 1; lastbin = uhi; }
        }
    }

    float salt = alpha * (sal + 1e-6f * (float)(1025 - U));

    // deterministic CTA tree reduce -> one partial per (k, quarter)
    red[tid] = salt;
    __syncthreads();
    for (int s = 128; s > 0; s >>= 1) {
        if (tid < s) red[tid] += red[tid + s];
        __syncthreads();
    }
    if (tid == 0) g_partial[blockIdx.x] = red[0];   // blockIdx.x = k*4 + quarter
}

// ---------- windowed Gaussian mag over FP contiguous bins (fixup only) ----------
__device__ __forceinline__ void eval_mag_group(
    float bf, float freq, float invf, float c0, float c1, float w,
    const float* __restrict__ harm, float m[FP])
{
    #pragma unroll
    for (int i = 0; i < FP; ++i) m[i] = 0.0f;
    int nlo = (int)ceilf((bf - w) * invf);
    int nhi = (int)floorf((bf + (float)(FP - 1) + w) * invf);
    nlo = max(1, nlo);
    nhi = min(H, nhi);
    for (int n = nlo; n <= nhi; ++n) {
        float nf = (float)n * freq;
        float cn = (n == 1) ? c0 : c1;
        float hn = harm[n - 1];
        #pragma unroll
        for (int i = 0; i < FP; ++i) {
            float d = (bf + (float)i) - nf;
            m[i] = fmaf(hn, ex2a(cn * d * d), m[i]);
        }
    }
}

__device__ __forceinline__ int tie_flag(const float* salA, int k) {
    float sk = salA[k];
    int fl = 0;
    #pragma unroll
    for (int j = 0; j < K; ++j)
        if (j != k && fabsf(sk - salA[j]) < SAL_MARGIN) fl = 1;
    return fl;
}

// ---------- kernel 3: exact-field salience fixup (only near-tied k) ----------
__global__ void fixup_kernel() {
    int k = blockIdx.x;
    int chunk = blockIdx.y;
    int tid = threadIdx.x;

    __shared__ float part[256];
    __shared__ float salA[K];
    __shared__ int   sfl;
    __shared__ float shh[H];
    __shared__ float red[256];

    part[tid] = g_partial[tid];
    __syncthreads();
    if (tid < K)
        salA[tid] = part[tid * 4] + part[tid * 4 + 1] + part[tid * 4 + 2] + part[tid * 4 + 3];
    __syncthreads();
    if (tid == 0) sfl = tie_flag(salA, k);
    __syncthreads();
    if (sfl == 0) return;

    if (tid < H) shh[tid] = g_harmS[k * H + tid];
    __syncthreads();

    float4 cc = g_KC[k];
    float acc = 0.0f;
    if (tid < NACT) {
        float bf = (float)(tid * FP);
        int t0 = chunk * TFIX;
        for (int t = t0; t < t0 + TFIX; ++t) {
            float4 p = g_P4[(k << 10) + t];
            float al = g_alphaK[(k << 10) + t];
            float m[FP];
            eval_mag_group(bf, p.x, p.y, cc.x, cc.y, cc.z, shh, m);
            float s = 0.0f;
            #pragma unroll
            for (int i = 0; i < FP; ++i)
                s += (m[i] > 0.0f) ? sqrta(fmaf(m[i], m[i], 1e-12f)) : 1e-6f;
            acc = fmaf(al, s, acc);
        }
    }
    red[tid] = acc;
    __syncthreads();
    for (int s = 128; s > 0; s >>= 1) {
        if (tid < s) red[tid] += red[tid + s];
        __syncthreads();
    }
    if (tid == 0) g_fix[k * NFIX + chunk] = red[0];
}

// ---------- kernel 4: combine + stable descending rank (one CTA) ----------
__global__ void combineorder_kernel() {
    __shared__ float salA[K];
    __shared__ float sal[K];
    int i = threadIdx.x;
    if (i < K)
        salA[i] = g_partial[i * 4] + g_partial[i * 4 + 1] + g_partial[i * 4 + 2] + g_partial[i * 4 + 3];
    __syncthreads();
    if (i < K) {
        float v;
        if (tie_flag(salA, i)) {
            v = 0.0f;
            #pragma unroll
            for (int c = 0; c < NFIX; ++c) v += g_fix[i * NFIX + c];
        } else v = salA[i];
        sal[i] = v;
    }
    __syncthreads();
    if (i < K) {
        float si = sal[i];
        int r = 0;
        #pragma unroll
        for (int j = 0; j < K; ++j) {
            float sj = sal[j];
            r += (sj > si) || (sj == si && j < i);
        }
        g_ord[r] = i;
    }
}

// ---------- kernel 5: ordered composite scan (window-empty skip) ----------
__global__ void scan_kernel(float* __restrict__ out, int capE) {
    int t = blockIdx.x;
    int tid = threadIdx.x;

    __shared__ int    shord[K];
    __shared__ float4 sh4[K];
    __shared__ float  shal[K];
    __shared__ float4 shc[K];
    __shared__ float  shh[K * H];

    if (tid < K) shord[tid] = g_ord[tid] & (K - 1);
    __syncthreads();
    if (tid < K) {
        int kk = shord[tid];
        int o = (kk << 10) + t;
        sh4[tid]  = g_P4[o];
        shal[tid] = g_alphaK[o];
        shc[tid]  = g_KC[kk];
    }
    for (int i = tid; i < K * H; i += blockDim.x)
        shh[i] = g_harmS[(shord[i >> 4] << 4) + (i & 15)];
    __syncthreads();

    if (tid >= NACT) return;
    float bf = (float)(tid * FP);

    float outr[FP], tt[FP];
    #pragma unroll
    for (int i = 0; i < FP; ++i) { outr[i] = 0.0f; tt[i] = 1.0f; }

    for (int j = 0; j < K; ++j) {
        float4 p  = sh4[j];
        float4 cc = shc[j];
        int nlo = max(1, (int)ceilf((bf - cc.z) * p.y));
        int nhi = min(H, (int)floorf((bf + (float)(FP - 1) + cc.z) * p.y));
        if (nlo > nhi) continue;

        float al = shal[j];
        const float* harm = &shh[j << 4];
        float m[FP];
        #pragma unroll
        for (int i = 0; i < FP; ++i) m[i] = 0.0f;
        for (int n = nlo; n <= nhi; ++n) {
            float nf = (float)n * p.x;
            float cn = (n == 1) ? cc.x : cc.y;
            float hn = harm[n - 1];
            #pragma unroll
            for (int i = 0; i < FP; ++i) {
                float d = (bf + (float)i) - nf;
                m[i] = fmaf(hn, ex2a(cn * d * d), m[i]);
            }
        }
        #pragma unroll
        for (int i = 0; i < FP; ++i) {
            float mv = m[i];
            float mc = (mv > 0.0f) ? sqrta(fmaf(mv, mv, 1e-12f)) : 1e-6f;
            float a  = fminf(al * mc, 1.0f);
            outr[i] = fmaf(tt[i] * mv, p.z, outr[i]);
            tt[i]   = fmaxf(fmaf(-a, tt[i], tt[i]), TFLOOR);
        }
    }

    int base = t * F + tid * FP;
    #pragma unroll
    for (int i = 0; i < FP; ++i) {
        int gi = base + i;
        if (gi < capE) out[gi] = outr[i];
    }
}

// ---------- launch ----------
extern "C" void kernel_launch(void* const* d_in, const int* in_sizes, int n_in,
                              void* d_out, int out_size) {
    const void* p[6];
    int s[6];
    for (int i = 0; i < 6; ++i) {
        if (i < n_in) { p[i] = d_in[i]; s[i] = in_sizes[i]; }
        else          { p[i] = 0; s[i] = 0; }
    }

    int capE = out_size;
    if (capE > T * F) capE = T * F;
    if (capE < 0) capE = 0;

    bindprep_kernel<<<1, 256>>>(p[0], s[0], p[1], s[1], p[2], s[2],
                                p[3], s[3], p[4], s[4], p[5], s[5]);
    ktsal_kernel<<<(K * T) / 256, 256>>>();
    fixup_kernel<<<dim3(K, NFIX), 256>>>();
    combineorder_kernel<<<1, 64>>>();
    scan_kernel<<<T, 224>>>((float*)d_out, capE);
}

// round 16
// speedup vs baseline: 2.1113x; 1.0344x over previous
#include <cuda_runtime.h>
#include <cuda_bf16.h>

#define K 64
#define T 1024
#define F 1025
#define NCTRL 257
#define H 16
#define FP 5
#define NACT 205
#define TFLOOR (1.0f - 0.9f)

__device__ __forceinline__ float ex2a(float x) {
    float y; asm("ex2.approx.f32 %0, %1;" : "=f"(y) : "f"(x)); return y;
}
__device__ __forceinline__ float sqrta(float x) {
    float y; asm("sqrt.approx.f32 %0, %1;" : "=f"(y) : "f"(x)); return y;
}

__device__ float4 g_P4[K * T];     // freq, 1/freq, alpha*cos(ph), alpha*sin(ph)
__device__ float  g_alphaK[K * T];
__device__ float4 g_KC[K];         // c0, c1, 8*sigma, sigma
__device__ float  g_harmS[K * H];
__device__ float  g_partial[K * 4];

__device__ __forceinline__ float ldin(const void* p, int i, int n, int isbf) {
    if (p == 0) return 0.0f;
    int j = i; if (j > n - 1) j = n - 1; if (j < 0) j = 0;
    if (isbf) return __bfloat162float(((const __nv_bfloat16*)p)[j]);
    return ((const float*)p)[j];
}

// ---------- kernel 1: classify + per-k constants + params + analytic salience ----------
// grid 256: CTA = (k, quarter); block 256 = t within quarter
__global__ void ktsal_kernel(const void* p0, int s0, const void* p1, int s1,
                             const void* p2, int s2, const void* p3, int s3,
                             const void* p4, int s4, const void* p5, int s5) {
    int bid = blockIdx.x;
    int k = bid >> 2;
    int q = bid & 3;
    int tid = threadIdx.x;
    int t = (q << 8) + tid;

    __shared__ float red[256];
    __shared__ float mabs[6];
    __shared__ int   nel[6];
    __shared__ int   sAbs, sTot;
    __shared__ const void* sp[6];
    __shared__ const void *bpath, *balpha, *bphase;
    __shared__ int   npathS, nalphaS, nphaseS, isbfS;
    __shared__ float sMu, shh[H], scumh[17];
    __shared__ float4 sKT1, sKT2;

    // --- slot setup (identical arithmetic to R14 bindprep) ---
    if (tid == 0) {
        sp[0] = p0; sp[1] = p1; sp[2] = p2; sp[3] = p3; sp[4] = p4; sp[5] = p5;
        int ss[6] = {s0, s1, s2, s3, s4, s5};
        for (int j = 0; j < 6; ++j) {
            int n = ss[j], ne;
            if      (n == K || n == K * 2 || n == K * 4)                         ne = K;
            else if (n == K * H || n == K * H * 2 || n == K * H * 4)             ne = K * H;
            else if (n == K * NCTRL || n == K * NCTRL * 2 || n == K * NCTRL * 4) ne = K * NCTRL;
            else                                                                  ne = 0;
            nel[j] = (sp[j] != 0) ? ne : 0;
        }
        sAbs = 0; sTot = 0;
    }
    __syncthreads();

    // --- dtype probe (bf16 vs f32) ---
    int myA = 0, myT = 0;
    for (int j = 0; j < 6; ++j) {
        int lw = nel[j] / 2; if (lw > 256) lw = 256;
        const unsigned* w = (const unsigned*)sp[j];
        if (w) for (int i = tid; i < lw; i += 256) {
            unsigned lo = w[i] & 0xFFFFu;
            if (lo != 0u && lo != 0x8000u) {
                int e = (int)((lo >> 7) & 0xFFu);
                ++myT;
                if (e < 90 || e > 164) ++myA;
            }
        }
    }
    if (myA) atomicAdd(&sAbs, myA);
    if (myT) atomicAdd(&sTot, myT);
    __syncthreads();
    int isbf = (sTot > 32 && sAbs * 100 < sTot * 35) ? 1 : 0;

    // --- mean|x| per slot ---
    for (int j = 0; j < 6; ++j) {
        int lim = nel[j] / 2; if (lim > 256) lim = 256;
        float s = 0.0f;
        if (sp[j]) for (int i = tid; i < lim; i += 256) s += fabsf(ldin(sp[j], i, lim, isbf));
        red[tid] = s;
        __syncthreads();
        for (int st = 128; st > 0; st >>= 1) {
            if (tid < st) red[tid] += red[tid + st];
            __syncthreads();
        }
        if (tid == 0) mabs[j] = (lim > 0) ? red[0] / (float)lim : -1.0f;
        __syncthreads();
    }

    // --- binding + per-k constants (thread 0) ---
    if (tid == 0) {
        int sm[2]; int nsm = 0;
        int ct[3]; int nct = 0;
        int ih = -1;
        for (int j = 0; j < 6; ++j) {
            if (nel[j] == K && nsm < 2)              sm[nsm++] = j;
            else if (nel[j] == K * H && ih < 0)      ih = j;
            else if (nel[j] == K * NCTRL && nct < 3) ct[nct++] = j;
        }
        const void *mu_p, *sig_p, *harm_p;
        int nmu, nsig, nharm;
        if (nsm == 2 && nct == 3 && ih >= 0) {
            int imu  = (mabs[sm[0]] >= mabs[sm[1]]) ? sm[0] : sm[1];
            int isig = (imu == sm[0]) ? sm[1] : sm[0];
            int a = ct[0], c = ct[1], d = ct[2];
            if (mabs[a] < mabs[c]) { int t_ = a; a = c; c = t_; }
            if (mabs[c] < mabs[d]) { int t_ = c; c = d; d = t_; }
            if (mabs[a] < mabs[c]) { int t_ = a; a = c; c = t_; }
            mu_p = sp[imu];  nmu = nel[imu];
            sig_p = sp[isig]; nsig = nel[isig];
            bpath = sp[a];  npathS = nel[a];
            balpha = sp[c]; nalphaS = nel[c];
            bphase = sp[d]; nphaseS = nel[d];
            harm_p = sp[ih]; nharm = nel[ih];
        } else {
            const void* fb = 0;
            for (int j = 0; j < 6; ++j) if (sp[j]) { fb = sp[j]; break; }
            mu_p  = sp[0] ? sp[0] : fb;  nmu  = (nel[0] > 0) ? nel[0] : 1;
            sig_p = sp[1] ? sp[1] : fb;  nsig = (nel[1] > 0) ? nel[1] : 1;
            bpath = sp[2] ? sp[2] : fb;  npathS = (nel[2] > 0) ? nel[2] : 1;
            balpha = sp[3] ? sp[3] : fb; nalphaS = (nel[3] > 0) ? nel[3] : 1;
            harm_p = sp[4] ? sp[4] : fb; nharm = (nel[4] > 0) ? nel[4] : 1;
            bphase = sp[5] ? sp[5] : fb; nphaseS = (nel[5] > 0) ? nel[5] : 1;
        }
        isbfS = isbf;
        sMu = ldin(mu_p, k, nmu, isbf);

        float sigma = __expf(ldin(sig_p, k, nsig, isbf));
        sigma = fminf(fmaxf(sigma, 0.5f), 60.0f);
        float c0 = -0.72134752044f / (sigma * sigma);
        if (q == 0) g_KC[k] = make_float4(c0, c0 / 0.49f, 8.0f * sigma, sigma);

        float l[H];
        float mx = -1e30f;
        #pragma unroll
        for (int h = 0; h < H; ++h) { l[h] = ldin(harm_p, k * H + h, nharm, isbf); mx = fmaxf(mx, l[h]); }
        float sum = 0.0f;
        #pragma unroll
        for (int h = 0; h < H; ++h) { l[h] = __expf(l[h] - mx); sum += l[h]; }
        float inv = 1.0f / sum;
        #pragma unroll
        for (int h = 0; h < H; ++h) { l[h] *= inv; shh[h] = l[h]; }

        float s1 = sigma, s2v = 0.7f * sigma;
        sKT1 = make_float4(s2v * 1.25331414f, 0.70710678f / s2v, 8.0f * s2v, s2v * 2.50662827f);
        sKT2 = make_float4(l[0] * s1 * 1.25331414f, 0.70710678f / s1, 8.0f * s1, s2v);

        float cum = 0.0f;
        scumh[0] = 0.0f; scumh[1] = 0.0f;
        #pragma unroll
        for (int n = 2; n <= H; ++n) { cum += l[n - 1]; scumh[n] = cum; }
    }
    __syncthreads();
    if (q == 0 && tid < H) g_harmS[k * H + tid] = shh[tid];

    // --- per-(k,t) interp + params ---
    int isb = isbfS;
    float pos = (float)t * (256.0f / 1023.0f);
    int lo = (int)pos;
    if (lo > NCTRL - 2) lo = NCTRL - 2;
    float fr  = pos - (float)lo;
    float omf = 1.0f - fr;
    int b0 = k * NCTRL + lo;
    int b1 = b0 + 1;

    float path = ldin(bpath,  b0, npathS,  isb) * omf + ldin(bpath,  b1, npathS,  isb) * fr;
    float av   = ldin(balpha, b0, nalphaS, isb) * omf + ldin(balpha, b1, nalphaS, isb) * fr;
    float ph   = ldin(bphase, b0, nphaseS, isb) * omf + ldin(bphase, b1, nphaseS, isb) * fr;

    float alpha = 1.0f / (1.0f + __expf(-av));
    float sp_, cp_;
    __sincosf(ph, &sp_, &cp_);

    float freq = sMu + path;
    freq = fminf(fmaxf(freq, 3.71519274f), 1024.0f);
    float invf = 1.0f / freq;

    int idx = (k << 10) + t;
    g_P4[idx]     = make_float4(freq, invf, alpha * cp_, alpha * sp_);
    g_alphaK[idx] = alpha;

    // --- analytic salience (identical to R14) ---
    float4 kt1 = sKT1;   // a2=s2*1.2533, isr2, w2, full2=s2*2.5066
    float4 kt2 = sKT2;   // a1h=h1*s1*1.2533, isr1, w1, s2
    float sal;

    if (freq >= kt2.z && freq <= 1024.0f - kt2.z) {
        sal = 2.0f * kt2.x;
    } else {
        sal = kt2.x * (erff((1024.5f - freq) * kt2.y) - erff((-0.5f - freq) * kt2.y));
    }

    int nloI = max(2, (int)ceilf(kt1.z * invf));
    int nhiI = min(H, (int)floorf((1024.0f - kt1.z) * invf));
    if (nhiI >= nloI) sal += kt1.w * (scumh[nhiI] - scumh[nloI - 1]);

    for (int n = 2; n < nloI && n <= H; ++n) {
        float c = (float)n * freq;
        sal += shh[n - 1] * kt1.x * (erff((1024.5f - c) * kt1.y) - erff((-0.5f - c) * kt1.y));
    }
    for (int n = max(nloI, nhiI + 1); n <= H; ++n) {
        float c = (float)n * freq;
        if (c - kt1.z > 1024.5f) break;
        sal += shh[n - 1] * kt1.x * (erff((1024.5f - c) * kt1.y) - erff((-0.5f - c) * kt1.y));
    }

    // exact union count of bins where any gaussian >= 1e-6
    float s1v = kt2.z * 0.125f, s2v = kt2.w;
    int U = 0, lastbin = -1;
    #pragma unroll 1
    for (int n = 1; n <= H; ++n) {
        float c  = (float)n * freq;
        float sn = (n == 1) ? s1v : s2v;
        if (c - 8.0f * sn > 1024.5f) break;
        float hn = shh[n - 1];
        if (hn > 1e-6f) {
            float dn = sn * sqrta(2.0f * (__logf(hn) + 13.8155106f));
            int ulo = (int)ceilf(c - dn);
            if (ulo < lastbin + 1) ulo = lastbin + 1;
            if (ulo < 0) ulo = 0;
            int uhi = (int)floorf(c + dn);
            if (uhi > 1024) uhi = 1024;
            if (uhi >= ulo) { U += uhi - ulo + 1; lastbin = uhi; }
        }
    }

    float salt = alpha * (sal + 1e-6f * (float)(1025 - U));

    // deterministic CTA tree reduce -> one partial per (k, quarter)
    red[tid] = salt;
    __syncthreads();
    for (int s = 128; s > 0; s >>= 1) {
        if (tid < s) red[tid] += red[tid + s];
        __syncthreads();
    }
    if (tid == 0) g_partial[bid] = red[0];
}

// ---------- kernel 2: in-CTA salience combine + rank + ordered composite scan ----------
__global__ void scan_kernel(float* __restrict__ out, int capE) {
    int t = blockIdx.x;
    int tid = threadIdx.x;

    __shared__ float part[256];
    __shared__ float sal[K];
    __shared__ int    shord[K];
    __shared__ float4 sh4[K];
    __shared__ float  shal[K];
    __shared__ float4 shc[K];
    __shared__ float  shh[K * H];

    for (int i = tid; i < 256; i += blockDim.x) part[i] = g_partial[i];
    __syncthreads();
    if (tid < K)
        sal[tid] = part[tid * 4] + part[tid * 4 + 1] + part[tid * 4 + 2] + part[tid * 4 + 3];
    __syncthreads();
    if (tid < K) {
        float si = sal[tid];
        int r = 0;
        #pragma unroll
        for (int j = 0; j < K; ++j) {
            float sj = sal[j];
            r += (sj > si) || (sj == si && j < tid);
        }
        shord[r] = tid;
    }
    __syncthreads();
    if (tid < K) {
        int kk = shord[tid];
        int o = (kk << 10) + t;
        sh4[tid]  = g_P4[o];
        shal[tid] = g_alphaK[o];
        shc[tid]  = g_KC[kk];
    }
    for (int i = tid; i < K * H; i += blockDim.x)
        shh[i] = g_harmS[(shord[i >> 4] << 4) + (i & 15)];
    __syncthreads();

    if (tid >= NACT) return;
    float bf = (float)(tid * FP);

    float outr[FP], tt[FP];
    #pragma unroll
    for (int i = 0; i < FP; ++i) { outr[i] = 0.0f; tt[i] = 1.0f; }

    for (int j = 0; j < K; ++j) {
        float4 p  = sh4[j];
        float4 cc = shc[j];
        int nlo = max(1, (int)ceilf((bf - cc.z) * p.y));
        int nhi = min(H, (int)floorf((bf + (float)(FP - 1) + cc.z) * p.y));
        if (nlo > nhi) continue;

        float al = shal[j];
        const float* harm = &shh[j << 4];
        float m[FP];
        #pragma unroll
        for (int i = 0; i < FP; ++i) m[i] = 0.0f;
        for (int n = nlo; n <= nhi; ++n) {
            float nf = (float)n * p.x;
            float cn = (n == 1) ? cc.x : cc.y;
            float hn = harm[n - 1];
            #pragma unroll
            for (int i = 0; i < FP; ++i) {
                float d = (bf + (float)i) - nf;
                m[i] = fmaf(hn, ex2a(cn * d * d), m[i]);
            }
        }
        #pragma unroll
        for (int i = 0; i < FP; ++i) {
            float mv = m[i];
            float mc = (mv > 0.0f) ? sqrta(fmaf(mv, mv, 1e-12f)) : 1e-6f;
            float a  = fminf(al * mc, 1.0f);
            outr[i] = fmaf(tt[i] * mv, p.z, outr[i]);
            tt[i]   = fmaxf(fmaf(-a, tt[i], tt[i]), TFLOOR);
        }
    }

    int base = t * F + tid * FP;
    #pragma unroll
    for (int i = 0; i < FP; ++i) {
        int gi = base + i;
        if (gi < capE) out[gi] = outr[i];
    }
}

// ---------- launch ----------
extern "C" void kernel_launch(void* const* d_in, const int* in_sizes, int n_in,
                              void* d_out, int out_size) {
    const void* p[6];
    int s[6];
    for (int i = 0; i < 6; ++i) {
        if (i < n_in) { p[i] = d_in[i]; s[i] = in_sizes[i]; }
        else          { p[i] = 0; s[i] = 0; }
    }

    int capE = out_size;
    if (capE > T * F) capE = T * F;
    if (capE < 0) capE = 0;

    ktsal_kernel<<<K * 4, 256>>>(p[0], s[0], p[1], s[1], p[2], s[2],
                                 p[3], s[3], p[4], s[4], p[5], s[5]);
    scan_kernel<<<T, 224>>>((float*)d_out, capE);
}